// round 2
// baseline (speedup 1.0000x reference)
#include <cuda_runtime.h>
#include <cuda_bf16.h>
#include <cstdint>

#define B_    32
#define VLEN_ 2048
#define H_    1024
#define DIM_  1024
#define C_    32
#define KC    1088              // 1024 (value) + 32 (conv feat) + 32 zero pad
#define M_    (B_*VLEN_)        // 65536

// ---------------- scratch (device globals: no runtime allocation) ----------------
__device__ __nv_bfloat16 g_valcat[(size_t)M_*KC];    // [65536][1088] bf16  (~142 MB)
__device__ __nv_bfloat16 g_wcat[(size_t)DIM_*KC];    // [1024][1088] bf16
__device__ float g_qbias[B_*DIM_];                   // qp[b,d] + bias[d]
__device__ float g_score[M_];
__device__ float g_attn[M_];
__device__ float g_context[B_*H_];

__device__ __forceinline__ uint32_t smem_u32(const void* p){
    return (uint32_t)__cvta_generic_to_shared(p);
}

// ---------------- prep: A matrix = [value(bf16) | conv_feat(bf16) | 0] ----------------
__global__ void build_valcat(const float* __restrict__ value,
                             const float* __restrict__ prev_attn,
                             const float* __restrict__ conv_w,
                             const float* __restrict__ conv_b) {
    int t = blockIdx.x*256 + threadIdx.x;               // one 16B chunk each
    const int CHUNKS = KC/8;                            // 136
    if (t >= M_*CHUNKS) return;
    int bv = t / CHUNKS, chunk = t % CHUNKS;
    __align__(16) __nv_bfloat16 o[8];
    if (chunk < 128) {
        const float4* s = reinterpret_cast<const float4*>(value + (size_t)bv*H_ + chunk*8);
        float4 x = s[0], y = s[1];
        o[0]=__float2bfloat16(x.x); o[1]=__float2bfloat16(x.y);
        o[2]=__float2bfloat16(x.z); o[3]=__float2bfloat16(x.w);
        o[4]=__float2bfloat16(y.x); o[5]=__float2bfloat16(y.y);
        o[6]=__float2bfloat16(y.z); o[7]=__float2bfloat16(y.w);
    } else if (chunk < 132) {
        int b = bv >> 11, v = bv & 2047;
        float pm = (v > 0)        ? prev_attn[b*VLEN_ + v - 1] : 0.f;
        float pc =                  prev_attn[b*VLEN_ + v];
        float pp = (v < VLEN_-1)  ? prev_attn[b*VLEN_ + v + 1] : 0.f;
        int c0 = (chunk-128)*8;
        #pragma unroll
        for (int j = 0; j < 8; j++) {
            int c = c0 + j;
            float cf = conv_w[c*3+0]*pm + conv_w[c*3+1]*pc + conv_w[c*3+2]*pp + conv_b[c];
            o[j] = __float2bfloat16(cf);
        }
    } else {
        #pragma unroll
        for (int j = 0; j < 8; j++) o[j] = __float2bfloat16(0.f);
    }
    *reinterpret_cast<uint4*>(g_valcat + (size_t)bv*KC + chunk*8) = *reinterpret_cast<uint4*>(o);
}

// ---------------- prep: B matrix = [w_v | w_loc | 0] ----------------
__global__ void build_wcat(const float* __restrict__ w_v, const float* __restrict__ w_loc) {
    int t = blockIdx.x*256 + threadIdx.x;
    const int CHUNKS = KC/8;
    if (t >= DIM_*CHUNKS) return;
    int d = t / CHUNKS, chunk = t % CHUNKS;
    __align__(16) __nv_bfloat16 o[8];
    if (chunk < 128) {
        const float* s = w_v + (size_t)d*H_ + chunk*8;
        #pragma unroll
        for (int j = 0; j < 8; j++) o[j] = __float2bfloat16(s[j]);
    } else if (chunk < 132) {
        const float* s = w_loc + (size_t)d*C_ + (chunk-128)*8;
        #pragma unroll
        for (int j = 0; j < 8; j++) o[j] = __float2bfloat16(s[j]);
    } else {
        #pragma unroll
        for (int j = 0; j < 8; j++) o[j] = __float2bfloat16(0.f);
    }
    *reinterpret_cast<uint4*>(g_wcat + (size_t)d*KC + chunk*8) = *reinterpret_cast<uint4*>(o);
}

// ---------------- prep: qbias[b,d] = query[b] . w_q[d] + bias[d] (fp32 exact) ----------------
__global__ void qbias_kernel(const float* __restrict__ query,
                             const float* __restrict__ w_q,
                             const float* __restrict__ bias) {
    int b = blockIdx.y;
    int warp = threadIdx.x >> 5, lane = threadIdx.x & 31;
    int d = blockIdx.x*8 + warp;
    const float* q = query + b*H_;
    const float* w = w_q + (size_t)d*H_;
    float acc = 0.f;
    for (int h = lane; h < H_; h += 32) acc += q[h]*w[h];
    #pragma unroll
    for (int o = 16; o; o >>= 1) acc += __shfl_xor_sync(0xffffffffu, acc, o);
    if (!lane) g_qbias[b*DIM_ + d] = acc + bias[d];
}

__global__ void zero_score() {
    int t = blockIdx.x*256 + threadIdx.x;
    if (t < M_) g_score[t] = 0.f;
}

// ---------------- fused GEMM + tanh + score reduction ----------------
// C[m,n] = sum_k A[m,k]*B[n,k] ; score[m] += sum_n tanh(C + qbias[b,n]) * w_score[n]
#define BM 128
#define BN 128
#define BK 32
#define KPAD 40   // padded smem row (bf16 elems) -> conflict-free ldmatrix

__device__ __forceinline__ void mma16816(float* c, const uint32_t* a, uint32_t b0, uint32_t b1) {
    asm volatile("mma.sync.aligned.m16n8k16.row.col.f32.bf16.bf16.f32 "
                 "{%0,%1,%2,%3}, {%4,%5,%6,%7}, {%8,%9}, {%0,%1,%2,%3};"
                 : "+f"(c[0]), "+f"(c[1]), "+f"(c[2]), "+f"(c[3])
                 : "r"(a[0]), "r"(a[1]), "r"(a[2]), "r"(a[3]), "r"(b0), "r"(b1));
}

__global__ __launch_bounds__(256, 2)
void gemm_score_kernel(const float* __restrict__ w_score) {
    __shared__ __nv_bfloat16 As[2][BM][KPAD];
    __shared__ __nv_bfloat16 Bs[2][BN][KPAD];
    __shared__ float qb_s[BN], ws_s[BN];

    const int t = threadIdx.x;
    const int warp = t >> 5, lane = t & 31;
    const int bn0 = blockIdx.x * BN;
    const int bm0 = blockIdx.y * BM;
    const int batch = bm0 >> 11;            // 2048 rows per batch, BM divides it

    if (t < BN) {
        qb_s[t] = g_qbias[batch*DIM_ + bn0 + t];
        ws_s[t] = w_score[bn0 + t];
    }

    const int lrow = t >> 2;      // 0..63
    const int lch  = t & 3;       // 0..3 (16B chunk within 64B k-slab)
    const __nv_bfloat16* Ag = g_valcat + (size_t)bm0*KC + lch*8;
    const __nv_bfloat16* Bg = g_wcat   + (size_t)bn0*KC + lch*8;

    const int wm = (warp >> 1) * 32;   // 4 warps along M
    const int wn = (warp & 1) * 64;    // 2 warps along N

    float acc[2][8][4];
    #pragma unroll
    for (int i = 0; i < 2; i++)
        #pragma unroll
        for (int j = 0; j < 8; j++)
            #pragma unroll
            for (int k = 0; k < 4; k++) acc[i][j][k] = 0.f;

    // prologue: stage 0
    {
        #pragma unroll
        for (int i = 0; i < 2; i++) {
            int r = lrow + i*64;
            uint32_t da = smem_u32(&As[0][r][lch*8]);
            asm volatile("cp.async.cg.shared.global [%0], [%1], 16;\n"
                         :: "r"(da), "l"(Ag + (size_t)r*KC));
            uint32_t db = smem_u32(&Bs[0][r][lch*8]);
            asm volatile("cp.async.cg.shared.global [%0], [%1], 16;\n"
                         :: "r"(db), "l"(Bg + (size_t)r*KC));
        }
        asm volatile("cp.async.commit_group;\n");
    }

    const int NK = KC / BK;  // 34
    for (int s = 0; s < NK; ++s) {
        asm volatile("cp.async.wait_group 0;\n");
        __syncthreads();
        if (s + 1 < NK) {
            int buf = (s+1) & 1, k0 = (s+1)*BK;
            #pragma unroll
            for (int i = 0; i < 2; i++) {
                int r = lrow + i*64;
                uint32_t da = smem_u32(&As[buf][r][lch*8]);
                asm volatile("cp.async.cg.shared.global [%0], [%1], 16;\n"
                             :: "r"(da), "l"(Ag + (size_t)r*KC + k0));
                uint32_t db = smem_u32(&Bs[buf][r][lch*8]);
                asm volatile("cp.async.cg.shared.global [%0], [%1], 16;\n"
                             :: "r"(db), "l"(Bg + (size_t)r*KC + k0));
            }
            asm volatile("cp.async.commit_group;\n");
        }
        int buf = s & 1;
        #pragma unroll
        for (int kk = 0; kk < 2; ++kk) {
            const int kb = kk*16;
            const int g = lane >> 3, idx = lane & 7;
            uint32_t a[2][4];
            #pragma unroll
            for (int mi = 0; mi < 2; mi++) {
                // A x4: g0:m0-7@k0, g1:m8-15@k0, g2:m0-7@k8, g3:m8-15@k8
                int row = wm + mi*16 + idx + 8*(g & 1);
                int col = kb + 8*(g >> 1);
                uint32_t addr = smem_u32(&As[buf][row][col]);
                asm volatile("ldmatrix.sync.aligned.m8n8.x4.shared.b16 {%0,%1,%2,%3}, [%4];"
                             : "=r"(a[mi][0]), "=r"(a[mi][1]), "=r"(a[mi][2]), "=r"(a[mi][3])
                             : "r"(addr));
            }
            uint32_t bfrag[4][4];
            #pragma unroll
            for (int ni = 0; ni < 4; ni++) {
                // B x4: g0:n0-7@k0, g1:n0-7@k8, g2:n8-15@k0, g3:n8-15@k8
                int row = wn + ni*16 + idx + 8*(g >> 1);
                int col = kb + 8*(g & 1);
                uint32_t addr = smem_u32(&Bs[buf][row][col]);
                asm volatile("ldmatrix.sync.aligned.m8n8.x4.shared.b16 {%0,%1,%2,%3}, [%4];"
                             : "=r"(bfrag[ni][0]), "=r"(bfrag[ni][1]), "=r"(bfrag[ni][2]), "=r"(bfrag[ni][3])
                             : "r"(addr));
            }
            #pragma unroll
            for (int mi = 0; mi < 2; mi++)
                #pragma unroll
                for (int ni = 0; ni < 4; ni++) {
                    mma16816(acc[mi][ni*2+0], a[mi], bfrag[ni][0], bfrag[ni][1]);
                    mma16816(acc[mi][ni*2+1], a[mi], bfrag[ni][2], bfrag[ni][3]);
                }
        }
    }

    // epilogue: tanh + weighted reduce over this CTA's 128 d-columns
    #pragma unroll
    for (int mi = 0; mi < 2; mi++) {
        float s0 = 0.f, s1 = 0.f;   // rows lane/4 and lane/4+8
        #pragma unroll
        for (int ni = 0; ni < 8; ni++) {
            int nc = wn + ni*8 + 2*(lane & 3);
            float qb0 = qb_s[nc], qb1 = qb_s[nc+1];
            float w0 = ws_s[nc],  w1 = ws_s[nc+1];
            s0 += tanhf(acc[mi][ni][0] + qb0)*w0 + tanhf(acc[mi][ni][1] + qb1)*w1;
            s1 += tanhf(acc[mi][ni][2] + qb0)*w0 + tanhf(acc[mi][ni][3] + qb1)*w1;
        }
        s0 += __shfl_xor_sync(0xffffffffu, s0, 1);
        s0 += __shfl_xor_sync(0xffffffffu, s0, 2);
        s1 += __shfl_xor_sync(0xffffffffu, s1, 1);
        s1 += __shfl_xor_sync(0xffffffffu, s1, 2);
        if ((lane & 3) == 0) {
            int m0 = bm0 + wm + mi*16 + (lane >> 2);
            atomicAdd(&g_score[m0],     s0);
            atomicAdd(&g_score[m0 + 8], s1);
        }
    }
}

// ---------------- sigmoid + normalize -> attn (also zero context) ----------------
__global__ void normalize_kernel(const float* __restrict__ b_score, float* __restrict__ attn_out,
                                 int write_attn) {
    int b = blockIdx.x, t = threadIdx.x;     // 256 threads, 2048 elems
    __shared__ float red[256];
    for (int h = t; h < H_; h += 256) g_context[b*H_ + h] = 0.f;
    float bs = b_score[0];
    float sv[8];
    float local = 0.f;
    #pragma unroll
    for (int i = 0; i < 8; i++) {
        float x = g_score[b*VLEN_ + t + i*256] + bs;
        float s = 1.f / (1.f + __expf(-x));
        sv[i] = s; local += s;
    }
    red[t] = local; __syncthreads();
    #pragma unroll
    for (int o = 128; o; o >>= 1) { if (t < o) red[t] += red[t+o]; __syncthreads(); }
    float inv = 1.f / red[0];
    #pragma unroll
    for (int i = 0; i < 8; i++) {
        float a = sv[i] * inv;
        g_attn[b*VLEN_ + t + i*256] = a;
        if (write_attn) attn_out[b*VLEN_ + t + i*256] = a;
    }
}

// ---------------- context[b,h] = sum_v attn[b,v] * value[b,v,h] ----------------
__global__ void context_kernel(const float* __restrict__ value) {
    int hc = blockIdx.x, b = blockIdx.y, vs = blockIdx.z;   // (4, B, 8)
    int h = hc*256 + threadIdx.x;
    __shared__ float a_s[256];
    a_s[threadIdx.x] = g_attn[b*VLEN_ + vs*256 + threadIdx.x];
    __syncthreads();
    const float* vp = value + ((size_t)b*VLEN_ + vs*256)*H_ + h;
    float acc = 0.f;
    #pragma unroll 8
    for (int v = 0; v < 256; v++) acc += a_s[v] * vp[(size_t)v*H_];
    atomicAdd(&g_context[b*H_ + h], acc);
}

// ---------------- output[b,h] = w_out[h] . [context | query] + b_out[h] ----------------
__global__ void output_kernel(const float* __restrict__ w_out, const float* __restrict__ b_out,
                              const float* __restrict__ query, float* __restrict__ out) {
    int b = blockIdx.y;
    int warp = threadIdx.x >> 5, lane = threadIdx.x & 31;
    int h = blockIdx.x*8 + warp;
    const float* wr = w_out + (size_t)h*(2*H_);
    const float* ctx = g_context + b*H_;
    const float* q = query + b*H_;
    float acc = 0.f;
    for (int k = lane; k < H_; k += 32) acc += wr[k]*ctx[k];
    for (int k = lane; k < H_; k += 32) acc += wr[H_+k]*q[k];
    #pragma unroll
    for (int o = 16; o; o >>= 1) acc += __shfl_xor_sync(0xffffffffu, acc, o);
    if (!lane) out[b*H_ + h] = acc + b_out[h];
}

// ---------------- launch ----------------
extern "C" void kernel_launch(void* const* d_in, const int* in_sizes, int n_in,
                              void* d_out, int out_size) {
    const float* query     = (const float*)d_in[0];
    const float* value     = (const float*)d_in[1];
    const float* prev_attn = (const float*)d_in[2];
    const float* conv_w    = (const float*)d_in[3];
    const float* conv_b    = (const float*)d_in[4];
    const float* w_loc     = (const float*)d_in[5];
    const float* w_q       = (const float*)d_in[6];
    const float* w_v       = (const float*)d_in[7];
    const float* bias      = (const float*)d_in[8];
    const float* w_score   = (const float*)d_in[9];
    const float* b_score   = (const float*)d_in[10];
    const float* w_out     = (const float*)d_in[11];
    const float* b_out     = (const float*)d_in[12];
    float* out = (float*)d_out;

    (void)in_sizes; (void)n_in; (void)w_loc; (void)w_v;

    build_valcat<<< (M_*(KC/8))/256, 256 >>>(value, prev_attn, conv_w, conv_b);
    build_wcat<<< (DIM_*(KC/8) + 255)/256, 256 >>>(w_v, w_loc);
    qbias_kernel<<< dim3(DIM_/8, B_), 256 >>>(query, w_q, bias);
    zero_score<<< M_/256, 256 >>>();
    gemm_score_kernel<<< dim3(DIM_/BN, M_/BM), 256 >>>(w_score);

    int write_attn = (out_size >= B_*H_ + M_) ? 1 : 0;   // output first, then attn
    normalize_kernel<<< B_, 256 >>>(b_score, out + B_*H_, write_attn);
    context_kernel<<< dim3(H_/256, B_, VLEN_/256), 256 >>>(value);
    output_kernel<<< dim3(H_/8, B_), 256 >>>(w_out, b_out, query, out);
}